// round 7
// baseline (speedup 1.0000x reference)
#include <cuda_runtime.h>
#include <cuda_bf16.h>
#include <math.h>

// ---------------- problem constants ----------------
#define BB    32
#define HH    28
#define WW    28
#define CC    192
#define HEADS 6
#define HD    32
#define KW    3
#define K2    9
#define NTOK  (BB*HH*WW)          // 25088
#define HID   576
#define ACOLS (K2*K2*HEADS)       // 486
#define APAD  (HEADS*K2*12)       // 648 padded a-row
#define SCALE 0.17677669529663687f
#define EPSLN 1e-5f

// ---------------- scratch (static device globals; no allocs) ----------------
__device__ float g_ln1[(size_t)NTOK*CC];
__device__ float g_v  [(size_t)NTOK*CC];
__device__ float g_a  [(size_t)NTOK*APAD];
__device__ float g_tmp[(size_t)NTOK*CC];
__device__ float g_x2 [(size_t)NTOK*CC];
__device__ float g_ln2[(size_t)NTOK*CC];
__device__ float g_h1 [(size_t)NTOK*HID];

// ---------------- LayerNorm: one warp per token ----------------
__global__ void ln_kernel(const float* __restrict__ x,
                          const float* __restrict__ g,
                          const float* __restrict__ b,
                          float* __restrict__ out)
{
    int warp = (blockIdx.x * blockDim.x + threadIdx.x) >> 5;
    int lane = threadIdx.x & 31;
    if (warp >= NTOK) return;
    const float* row = x + (size_t)warp * CC;
    float vals[6];
    float s = 0.f;
    #pragma unroll
    for (int i = 0; i < 6; i++) { vals[i] = row[lane + 32*i]; s += vals[i]; }
    #pragma unroll
    for (int o = 16; o > 0; o >>= 1) s += __shfl_xor_sync(0xffffffffu, s, o);
    float mean = s * (1.f/CC);
    float vs = 0.f;
    #pragma unroll
    for (int i = 0; i < 6; i++) { float d = vals[i]-mean; vs += d*d; }
    #pragma unroll
    for (int o = 16; o > 0; o >>= 1) vs += __shfl_xor_sync(0xffffffffu, vs, o);
    float r = rsqrtf(vs * (1.f/CC) + EPSLN);
    float* orow = out + (size_t)warp * CC;
    #pragma unroll
    for (int i = 0; i < 6; i++) {
        int c = lane + 32*i;
        orow[c] = (vals[i]-mean) * r * g[c] + b[c];
    }
}

// ---------------- TF32 tensor-core GEMM (cp.async, 2-stage, 256x64 tile) ----------------
#define SA_ST 36   // 36 % 32 == 4 -> conflict-free A fragment reads
#define SB_ST 72   // >= 64 cols, 72 % 32 == 8 -> conflict-free B fragment reads
#define SA_SZ (256*SA_ST)
#define SB_SZ (32*SB_ST)
#define STG_WORDS (SA_SZ + SB_SZ)
#define GEMM_SMEM (2*STG_WORDS*4)  // 92160 bytes

__device__ __forceinline__ void cp16(unsigned dst, const void* src) {
    asm volatile("cp.async.ca.shared.global [%0], [%1], 16;" :: "r"(dst), "l"(src));
}
__device__ __forceinline__ void cp8z(unsigned dst, const void* src, int nbytes) {
    asm volatile("cp.async.ca.shared.global [%0], [%1], 8, %2;" :: "r"(dst), "l"(src), "r"(nbytes));
}
__device__ __forceinline__ void cp_commit() {
    asm volatile("cp.async.commit_group;");
}

// remap 0..485 -> padded [head][i][12] offset
__device__ __forceinline__ int a_remap(int c) {
    int h = c / 81;
    int r = c - 81*h;
    int i = r / 9;
    int j = r - 9*i;
    return h*108 + i*12 + j;
}

// EPI: 0 bias-only, 1 bias+gelu, 2 bias+residual, 3 bias + padded-layout store (stride APAD)
template<int EPI>
__global__ __launch_bounds__(256, 2)
void gemm_tf32_kernel(const float* __restrict__ A,
                      const float* __restrict__ Bw,
                      const float* __restrict__ bias,
                      const float* __restrict__ res,
                      float* __restrict__ out,
                      int Kd, int M)
{
    extern __shared__ unsigned smem[];
    const unsigned smem_base = (unsigned)__cvta_generic_to_shared(smem);

    const int tid  = threadIdx.x;
    const int lane = tid & 31;
    const int w    = tid >> 5;
    const int wr   = w & 3;
    const int wc   = w >> 2;
    const int gid  = lane >> 2;
    const int tig  = lane & 3;
    const int row0 = blockIdx.y * 256;
    const int col0 = blockIdx.x * 64;

    float acc[4][4][4];
    #pragma unroll
    for (int mt = 0; mt < 4; mt++)
        #pragma unroll
        for (int nt = 0; nt < 4; nt++)
            #pragma unroll
            for (int i = 0; i < 4; i++) acc[mt][nt][i] = 0.f;

    const int nk = Kd / 32;

    auto issue_stage = [&](int s) {
        int kb = s * 32;
        unsigned base = smem_base + (unsigned)((s & 1) * STG_WORDS * 4);
        #pragma unroll
        for (int i = 0; i < 8; i++) {
            int f = tid + 256*i;
            int r = f >> 3, kq = (f & 7) * 4;
            cp16(base + (unsigned)((r*SA_ST + kq)*4),
                 &A[(size_t)(row0 + r) * Kd + kb + kq]);
        }
        unsigned bbase = base + (unsigned)(SA_SZ*4);
        #pragma unroll
        for (int i = 0; i < 4; i++) {
            int f = tid + 256*i;
            int kr = f >> 5, c2 = f & 31;
            int col = col0 + c2*2;
            int rem = M - col;
            int nb = rem >= 2 ? 8 : (rem == 1 ? 4 : 0);
            int colc = col < M - 2 ? col : M - 2;
            cp8z(bbase + (unsigned)((kr*SB_ST + c2*2)*4),
                 &Bw[(size_t)(kb + kr) * M + colc], nb);
        }
    };

    issue_stage(0); cp_commit();
    issue_stage(1); cp_commit();

    for (int it = 0; it < nk; it++) {
        if (it + 1 < nk) asm volatile("cp.async.wait_group 1;" ::: "memory");
        else             asm volatile("cp.async.wait_group 0;" ::: "memory");
        __syncthreads();

        const unsigned* cA = (const unsigned*)smem + (it & 1) * STG_WORDS;
        const unsigned* cB = cA + SA_SZ;
        #pragma unroll
        for (int ks = 0; ks < 4; ks++) {
            const int k0 = ks * 8;
            unsigned af[4][4];
            #pragma unroll
            for (int mt = 0; mt < 4; mt++) {
                int r = wr*64 + mt*16 + gid;
                af[mt][0] = cA[ r     *SA_ST + k0 + tig    ];
                af[mt][1] = cA[(r + 8)*SA_ST + k0 + tig    ];
                af[mt][2] = cA[ r     *SA_ST + k0 + tig + 4];
                af[mt][3] = cA[(r + 8)*SA_ST + k0 + tig + 4];
            }
            unsigned bf[4][2];
            #pragma unroll
            for (int nt = 0; nt < 4; nt++) {
                int c = wc*32 + nt*8 + gid;
                bf[nt][0] = cB[(k0 + tig    )*SB_ST + c];
                bf[nt][1] = cB[(k0 + tig + 4)*SB_ST + c];
            }
            #pragma unroll
            for (int mt = 0; mt < 4; mt++)
                #pragma unroll
                for (int nt = 0; nt < 4; nt++) {
                    asm volatile(
                      "mma.sync.aligned.m16n8k8.row.col.f32.tf32.tf32.f32 "
                      "{%0,%1,%2,%3},{%4,%5,%6,%7},{%8,%9},{%0,%1,%2,%3};"
                      : "+f"(acc[mt][nt][0]), "+f"(acc[mt][nt][1]),
                        "+f"(acc[mt][nt][2]), "+f"(acc[mt][nt][3])
                      : "r"(af[mt][0]), "r"(af[mt][1]),
                        "r"(af[mt][2]), "r"(af[mt][3]),
                        "r"(bf[nt][0]), "r"(bf[nt][1]));
                }
        }
        __syncthreads();
        if (it + 2 < nk) { issue_stage(it + 2); cp_commit(); }
    }

    // epilogue
    #pragma unroll
    for (int mt = 0; mt < 4; mt++) {
        #pragma unroll
        for (int nt = 0; nt < 4; nt++) {
            int r0  = row0 + wr*64 + mt*16 + gid;
            int col = col0 + wc*32 + nt*8 + tig*2;
            if (col < M) {
                float2 bb = make_float2(0.f, 0.f);
                if (bias) bb = *(const float2*)&bias[col];
                #pragma unroll
                for (int half = 0; half < 2; half++) {
                    int row = r0 + half*8;
                    float2 vv;
                    vv.x = acc[mt][nt][half*2    ] + bb.x;
                    vv.y = acc[mt][nt][half*2 + 1] + bb.y;
                    if (EPI == 1) {
                        vv.x = 0.5f * vv.x * (1.0f + erff(vv.x * 0.70710678118654752f));
                        vv.y = 0.5f * vv.y * (1.0f + erff(vv.y * 0.70710678118654752f));
                        *(float2*)&out[(size_t)row * M + col] = vv;
                    } else if (EPI == 2) {
                        float2 rr = *(const float2*)&res[(size_t)row * M + col];
                        vv.x += rr.x; vv.y += rr.y;
                        *(float2*)&out[(size_t)row * M + col] = vv;
                    } else if (EPI == 3) {
                        float* orow = out + (size_t)row * APAD;
                        orow[a_remap(col)]     = vv.x;
                        orow[a_remap(col + 1)] = vv.y;
                    } else {
                        *(float2*)&out[(size_t)row * M + col] = vv;
                    }
                }
            }
        }
    }
}

// ---------------- fused outlook attention + fold, head-coarsened ----------------
// a is in padded layout [t][head][i][12]; probs padded to 12-float rows.
#define PR_ROW 12
#define PR_HEAD (K2*PR_ROW)            // 108
#define PR_WARP (HEADS*PR_HEAD)        // 648

__global__ void attn_fold_kernel(const float* __restrict__ a,
                                 const float* __restrict__ v,
                                 float* __restrict__ tmp)
{
    __shared__ float probs[8][PR_WARP];
    int warp = threadIdx.x >> 5;
    int lane = threadIdx.x & 31;
    int t = blockIdx.x * 8 + warp;
    int b  = t / (HH*WW);
    int pq = t % (HH*WW);
    int p = pq / WW, q = pq % WW;

    // ---- phase A: 54 softmax rows over 27 lanes (2 each), vectorized IO ----
    if (lane < 27) {
        #pragma unroll
        for (int rep = 0; rep < 2; rep++) {
            int rr = lane + rep*27;            // 0..53
            int head = rr / K2;
            int i    = rr - head*K2;
            int di = i / KW, dj = i - di*KW;
            int tp = p + 1 - di, tq = q + 1 - dj;
            float* dst = &probs[warp][head*PR_HEAD + i*PR_ROW];
            if ((unsigned)tp < (unsigned)HH && (unsigned)tq < (unsigned)WW) {
                int ts = (b*HH + tp) * WW + tq;
                const float* ar = a + (size_t)ts * APAD + head*108 + i*12;
                float4 x0 = *(const float4*)ar;
                float4 x1 = *(const float4*)(ar + 4);
                float  x8 = ar[8];
                float vv[K2] = {x0.x, x0.y, x0.z, x0.w, x1.x, x1.y, x1.z, x1.w, x8};
                float mx = -INFINITY;
                #pragma unroll
                for (int j = 0; j < K2; j++) { vv[j] *= SCALE; mx = fmaxf(mx, vv[j]); }
                float s = 0.f;
                #pragma unroll
                for (int j = 0; j < K2; j++) { vv[j] = __expf(vv[j] - mx); s += vv[j]; }
                float inv = __fdividef(1.f, s);
                *(float4*)dst       = make_float4(vv[0]*inv, vv[1]*inv, vv[2]*inv, vv[3]*inv);
                *(float4*)(dst + 4) = make_float4(vv[4]*inv, vv[5]*inv, vv[6]*inv, vv[7]*inv);
                dst[8] = vv[8]*inv;
            } else {
                float4 z = make_float4(0.f, 0.f, 0.f, 0.f);
                *(float4*)dst = z;
                *(float4*)(dst + 4) = z;
                dst[8] = 0.f;
            }
        }
    }
    __syncwarp();

    // ---- phase B: window gather, separable index precompute ----
    int rowbase[5], coloff[5];
    unsigned rmask = 0, cmask = 0;
    #pragma unroll
    for (int d = 0; d < 5; d++) {
        int vp = p + d - 2, vq = q + d - 2;
        bool rok = (unsigned)vp < (unsigned)HH;
        bool cok = (unsigned)vq < (unsigned)WW;
        rowbase[d] = rok ? ((b*HH + vp) * WW) * CC : 0;
        coloff[d]  = cok ? vq * CC : 0;
        if (rok) rmask |= (1u << d);
        if (cok) cmask |= (1u << d);
    }

    for (int head = 0; head < HEADS; head++) {
        const int ch = head*HD + lane;
        float vr[25];
        #pragma unroll
        for (int dp = 0; dp < 5; dp++) {
            #pragma unroll
            for (int dq = 0; dq < 5; dq++) {
                bool ok = ((rmask >> dp) & 1u) && ((cmask >> dq) & 1u);
                vr[dp*5 + dq] = ok ? v[(size_t)(rowbase[dp] + coloff[dq] + ch)] : 0.f;
            }
        }
        const float* prh = &probs[warp][head*PR_HEAD];
        float acc = 0.f;
        #pragma unroll
        for (int i = 0; i < K2; i++) {
            int di = i / KW, dj = i - di*KW;
            const float4* rp = (const float4*)(prh + i*PR_ROW);
            float4 r0 = rp[0], r1 = rp[1];
            float  r2 = prh[i*PR_ROW + 8];
            float pr[K2] = {r0.x, r0.y, r0.z, r0.w, r1.x, r1.y, r1.z, r1.w, r2};
            const float* vb = &vr[(2 - di)*5 + (2 - dj)];
            #pragma unroll
            for (int j = 0; j < K2; j++) {
                int ei = j / KW, ej = j - ei*KW;
                acc = fmaf(pr[j], vb[ei*5 + ej], acc);
            }
        }
        tmp[(size_t)t * CC + ch] = acc;
    }
}

// ---------------- launcher ----------------
extern "C" void kernel_launch(void* const* d_in, const int* in_sizes, int n_in,
                              void* d_out, int out_size)
{
    const float* x     = (const float*)d_in[0];
    const float* ln1_g = (const float*)d_in[1];
    const float* ln1_b = (const float*)d_in[2];
    const float* Wv    = (const float*)d_in[3];
    const float* Wa    = (const float*)d_in[4];
    const float* ba    = (const float*)d_in[5];
    const float* Wp    = (const float*)d_in[6];
    const float* bp    = (const float*)d_in[7];
    const float* ln2_g = (const float*)d_in[8];
    const float* ln2_b = (const float*)d_in[9];
    const float* W1    = (const float*)d_in[10];
    const float* b1    = (const float*)d_in[11];
    const float* W2    = (const float*)d_in[12];
    const float* b2    = (const float*)d_in[13];
    float* out = (float*)d_out;

    float *p_ln1, *p_v, *p_a, *p_tmp, *p_x2, *p_ln2, *p_h1;
    cudaGetSymbolAddress((void**)&p_ln1, g_ln1);
    cudaGetSymbolAddress((void**)&p_v,   g_v);
    cudaGetSymbolAddress((void**)&p_a,   g_a);
    cudaGetSymbolAddress((void**)&p_tmp, g_tmp);
    cudaGetSymbolAddress((void**)&p_x2,  g_x2);
    cudaGetSymbolAddress((void**)&p_ln2, g_ln2);
    cudaGetSymbolAddress((void**)&p_h1,  g_h1);

    cudaFuncSetAttribute(gemm_tf32_kernel<0>, cudaFuncAttributeMaxDynamicSharedMemorySize, GEMM_SMEM);
    cudaFuncSetAttribute(gemm_tf32_kernel<1>, cudaFuncAttributeMaxDynamicSharedMemorySize, GEMM_SMEM);
    cudaFuncSetAttribute(gemm_tf32_kernel<2>, cudaFuncAttributeMaxDynamicSharedMemorySize, GEMM_SMEM);
    cudaFuncSetAttribute(gemm_tf32_kernel<3>, cudaFuncAttributeMaxDynamicSharedMemorySize, GEMM_SMEM);

    const int RB = NTOK / 256;   // 98

    ln_kernel<<<NTOK/8, 256>>>(x, ln1_g, ln1_b, p_ln1);
    gemm_tf32_kernel<0><<<dim3((CC+63)/64, RB), 256, GEMM_SMEM>>>(p_ln1, Wv, nullptr, nullptr, p_v, CC, CC);
    gemm_tf32_kernel<3><<<dim3((ACOLS+63)/64, RB), 256, GEMM_SMEM>>>(p_ln1, Wa, ba, nullptr, p_a, CC, ACOLS);
    attn_fold_kernel<<<NTOK/8, 256>>>(p_a, p_v, p_tmp);
    gemm_tf32_kernel<2><<<dim3((CC+63)/64, RB), 256, GEMM_SMEM>>>(p_tmp, Wp, bp, x, p_x2, CC, CC);
    ln_kernel<<<NTOK/8, 256>>>(p_x2, ln2_g, ln2_b, p_ln2);
    gemm_tf32_kernel<1><<<dim3((HID+63)/64, RB), 256, GEMM_SMEM>>>(p_ln2, W1, b1, nullptr, p_h1, CC, HID);
    gemm_tf32_kernel<2><<<dim3((CC+63)/64, RB), 256, GEMM_SMEM>>>(p_h1, W2, b2, p_x2, out, HID, CC);
}